// round 14
// baseline (speedup 1.0000x reference)
#include <cuda_runtime.h>
#include <cstdint>

#define NPOINTS     500000
#define NWAVE       128
#define NOFFSETS    50

#define TPB         128
#define NBLK        1184            // 8 blocks/SM on 148 SMs (R2's proven tail size)
#define QUOT        422             // NPOINTS / NBLK
#define REMR        352             // NPOINTS - QUOT*NBLK
#define TILE        424             // sdist capacity >= 423

#define SPTS        8               // points per pipeline stage
#define STBYTES     (SPTS * NWAVE * 4)   // 4096 B per stage
#define NSTG        53              // ceil(423/8) == ceil(422/8) == 53
#define NBUF        4               // pipeline depth 3

#define TWO_PI      6.283185307179586f

// Transposed layout [wave][block]: tail reads contiguous rows.
__device__ float g_partialC[NWAVE * NBLK];
__device__ float g_partialS[NWAVE * NBLK];
__device__ float g_m[NWAVE];

__global__ __launch_bounds__(TPB, 8)
void accum_kernel(const float2* __restrict__ xy,
                  const float*  __restrict__ tid,
                  const float*  __restrict__ center,
                  const float*  __restrict__ wavelength)
{
    __shared__ __align__(16) float stile[NBUF][SPTS * NWAVE];  // 16 KB ring
    __shared__ __align__(16) float sdist[TILE];

    const int w    = threadIdx.x;
    const int b    = blockIdx.x;
    const int base = b * QUOT + min(b, REMR);
    const int n    = QUOT + (b < REMR ? 1 : 0);   // 422 or 423

    // Per-thread bases; hot-path cp.async uses only immediate offsets.
    const char* __restrict__ gthr =
        (const char*)(tid + (size_t)base * NWAVE) + threadIdx.x * 16;
    uint32_t sb[NBUF];
    #pragma unroll
    for (int k = 0; k < NBUF; k++)
        sb[k] = (uint32_t)__cvta_generic_to_shared(&stile[k][0]) + threadIdx.x * 16;

    // 4KB stage = 2x16B per thread. Stages 0..NSTG-2 are always full.
    auto issue_full = [&](const char* g, uint32_t d) {
        asm volatile("cp.async.cg.shared.global [%0], [%1], 16;\n"
                     :: "r"(d), "l"(g));
        asm volatile("cp.async.cg.shared.global [%0], [%1], 16;\n"
                     :: "r"(d + 2048), "l"(g + 2048));
        asm volatile("cp.async.commit_group;\n");
    };
    auto issue_tail = [&](const char* g, uint32_t d, int s) {
        const int r0 = s * SPTS + (threadIdx.x >> 5);     // 512B per point-row
        if (r0 < n)
            asm volatile("cp.async.cg.shared.global [%0], [%1], 16;\n"
                         :: "r"(d), "l"(g));
        if (r0 + 4 < n)
            asm volatile("cp.async.cg.shared.global [%0], [%1], 16;\n"
                         :: "r"(d + 2048), "l"(g + 2048));
        asm volatile("cp.async.commit_group;\n");
    };

    // Prologue: 3 stages in flight before any compute.
    issue_full(gthr,               sb[0]);
    issue_full(gthr + STBYTES,     sb[1]);
    issue_full(gthr + 2 * STBYTES, sb[2]);
    const char* gnext = gthr + 3 * STBYTES;

    // Overlap: compute dist while stages stream in.
    const float kw = TWO_PI / wavelength[w];
    const float cx = center[0];
    const float cy = center[1];
    for (int k = threadIdx.x; k < n; k += TPB) {
        const float2 v = xy[base + k];
        const float dx = v.x - cx;
        const float dy = v.y - cy;
        sdist[k] = sqrtf(fmaf(dx, dx, dy * dy));
    }

    float accC = 0.0f;
    float accS = 0.0f;

    for (int s = 0; s < NSTG; s++) {
        // Drain so stage s is complete for THIS thread's copies...
        if (s + 2 < NSTG)
            asm volatile("cp.async.wait_group 2;\n" ::: "memory");
        else if (s + 1 < NSTG)
            asm volatile("cp.async.wait_group 1;\n" ::: "memory");
        else
            asm volatile("cp.async.wait_group 0;\n" ::: "memory");
        __syncthreads();   // ...and for everyone; also frees buffer (s-1)&3

        // Refill ahead of compute: buffer (s+3)&3 == (s-1)&3, just freed.
        if (s + 3 < NSTG) {
            if (s + 3 == NSTG - 1) issue_tail(gnext, sb[(s + 3) & 3], s + 3);
            else                   issue_full(gnext, sb[(s + 3) & 3]);
            gnext += STBYTES;
        }

        const int cnt = min(SPTS, n - s * SPTS);
        const float* __restrict__ tb = &stile[s & 3][w];

        if (cnt == SPTS) {
            const float4* __restrict__ dp4 = (const float4*)&sdist[s * SPTS];
            const float4 dA = dp4[0];
            const float4 dB = dp4[1];
            float sn, cs, t;
            t = tb[0 * NWAVE]; __sincosf(dA.x * kw, &sn, &cs); accC = fmaf(cs, t, accC); accS = fmaf(sn, t, accS);
            t = tb[1 * NWAVE]; __sincosf(dA.y * kw, &sn, &cs); accC = fmaf(cs, t, accC); accS = fmaf(sn, t, accS);
            t = tb[2 * NWAVE]; __sincosf(dA.z * kw, &sn, &cs); accC = fmaf(cs, t, accC); accS = fmaf(sn, t, accS);
            t = tb[3 * NWAVE]; __sincosf(dA.w * kw, &sn, &cs); accC = fmaf(cs, t, accC); accS = fmaf(sn, t, accS);
            t = tb[4 * NWAVE]; __sincosf(dB.x * kw, &sn, &cs); accC = fmaf(cs, t, accC); accS = fmaf(sn, t, accS);
            t = tb[5 * NWAVE]; __sincosf(dB.y * kw, &sn, &cs); accC = fmaf(cs, t, accC); accS = fmaf(sn, t, accS);
            t = tb[6 * NWAVE]; __sincosf(dB.z * kw, &sn, &cs); accC = fmaf(cs, t, accC); accS = fmaf(sn, t, accS);
            t = tb[7 * NWAVE]; __sincosf(dB.w * kw, &sn, &cs); accC = fmaf(cs, t, accC); accS = fmaf(sn, t, accS);
        } else {
            const float* __restrict__ dp = &sdist[s * SPTS];
            for (int i = 0; i < cnt; i++) {
                const float t = tb[i * NWAVE];
                float sn, cs;
                __sincosf(dp[i] * kw, &sn, &cs);
                accC = fmaf(cs, t, accC);
                accS = fmaf(sn, t, accS);
            }
        }
        // no second barrier: next iteration's barrier protects buffer reuse
    }

    // Transposed (column) store: scattered but tiny; tail reads contiguous.
    g_partialC[w * NBLK + b] = accC;
    g_partialS[w * NBLK + b] = accS;
}

// Tail: R2's exact structure and size (measured ~3.6us wall at NBLK=1184).
__global__ __launch_bounds__(256)
void reduce_kernel()
{
    __shared__ float sc[256];
    __shared__ float ss[256];

    const int w = blockIdx.x;
    const int t = threadIdx.x;

    const float* __restrict__ pc = g_partialC + (size_t)w * NBLK;
    const float* __restrict__ ps = g_partialS + (size_t)w * NBLK;

    float c = 0.0f, s = 0.0f;
    for (int bb = t; bb < NBLK; bb += 256) {   // contiguous rows, coalesced
        c += pc[bb];
        s += ps[bb];
    }
    sc[t] = c;
    ss[t] = s;
    __syncthreads();

    #pragma unroll
    for (int stride = 128; stride > 0; stride >>= 1) {
        if (t < stride) { sc[t] += sc[t + stride]; ss[t] += ss[t + stride]; }
        __syncthreads();
    }

    if (t == 0) {
        const float C = sc[0] * (1.0f / (float)NPOINTS);
        const float S = ss[0] * (1.0f / (float)NPOINTS);
        float m = -3.402823466e38f;
        #pragma unroll
        for (int i = 0; i < NOFFSETS; i++) {
            const float o = (float)i * (TWO_PI / (float)(NOFFSETS - 1));
            const float v = C * cosf(o) - S * sinf(o);
            m = fmaxf(m, v);
        }
        g_m[w] = m;
    }
}

__global__ void final_sum_kernel(float* __restrict__ out)
{
    __shared__ float sm[NWAVE];
    const int w = threadIdx.x;
    sm[w] = g_m[w];
    __syncthreads();

    #pragma unroll
    for (int stride = NWAVE / 2; stride > 0; stride >>= 1) {
        if (w < stride) sm[w] += sm[w + stride];
        __syncthreads();
    }
    if (w == 0) out[0] = -sm[0];
}

extern "C" void kernel_launch(void* const* d_in, const int* in_sizes, int n_in,
                              void* d_out, int out_size)
{
    const float2* xy         = (const float2*)d_in[0];  // [500000, 2]
    const float*  tid        = (const float*) d_in[1];  // [500000, 128]
    const float*  center     = (const float*) d_in[2];  // [2]
    const float*  wavelength = (const float*) d_in[3];  // [128]
    float* out = (float*)d_out;

    accum_kernel<<<NBLK, TPB>>>(xy, tid, center, wavelength);
    reduce_kernel<<<NWAVE, 256>>>();
    final_sum_kernel<<<1, NWAVE>>>(out);
}

// round 15
// speedup vs baseline: 1.1231x; 1.1231x over previous
#include <cuda_runtime.h>
#include <cstdint>

#define NPOINTS     500000
#define NWAVE       128
#define NOFFSETS    50

#define TPB         128
#define NBLK        1184            // 8 blocks/SM on 148 SMs (low-tail-gap size)
#define QUOT        422             // NPOINTS / NBLK
#define REMR        352             // NPOINTS - QUOT*NBLK
#define TILE        424             // sdist capacity >= 423

#define SPTS        16              // points per pipeline stage (R12-proven)
#define STBYTES     (SPTS * NWAVE * 4)   // 8192 B per stage
#define NSTG        27              // ceil(423/16); stages 0..25 always full

#define TWO_PI      6.283185307179586f

// Transposed layout [wave][block]: tail reads contiguous rows (R2 layout).
__device__ float g_partialC[NWAVE * NBLK];
__device__ float g_partialS[NWAVE * NBLK];
__device__ float g_m[NWAVE];

__global__ __launch_bounds__(TPB, 8)
void accum_kernel(const float2* __restrict__ xy,
                  const float*  __restrict__ tid,
                  const float*  __restrict__ center,
                  const float*  __restrict__ wavelength)
{
    __shared__ __align__(16) float stile[2][SPTS * NWAVE];  // 16 KB double buffer
    __shared__ __align__(16) float sdist[TILE];

    const int w    = threadIdx.x;
    const int b    = blockIdx.x;
    const int base = b * QUOT + min(b, REMR);
    const int n    = QUOT + (b < REMR ? 1 : 0);   // 422 or 423

    // Hoisted per-thread bases: hot-path cp.async uses only immediate offsets.
    const char* __restrict__ gthr =
        (const char*)(tid + (size_t)base * NWAVE) + threadIdx.x * 16;
    const uint32_t sb0 = (uint32_t)__cvta_generic_to_shared(&stile[0][0]) + threadIdx.x * 16;
    const uint32_t sb1 = (uint32_t)__cvta_generic_to_shared(&stile[1][0]) + threadIdx.x * 16;

    // Full 8KB stage: 4x16B per thread, no predicates (stages 0..25 full).
    auto issue_full = [&](int s, int buf) {
        const uint32_t d = buf ? sb1 : sb0;
        const char* g = gthr + (size_t)s * STBYTES;
        #pragma unroll
        for (int k = 0; k < 4; k++) {
            asm volatile("cp.async.cg.shared.global [%0], [%1], 16;\n"
                         :: "r"(d + k * 2048), "l"(g + k * 2048));
        }
        asm volatile("cp.async.commit_group;\n");
    };
    // Last (partial) stage: predicate on point row.
    auto issue_tail = [&](int s, int buf) {
        const uint32_t d = buf ? sb1 : sb0;
        const char* g = gthr + (size_t)s * STBYTES;
        const int trow = threadIdx.x >> 5;               // 512B per point-row
        #pragma unroll
        for (int k = 0; k < 4; k++) {
            if (s * SPTS + trow + 4 * k < n) {
                asm volatile("cp.async.cg.shared.global [%0], [%1], 16;\n"
                             :: "r"(d + k * 2048), "l"(g + k * 2048));
            }
        }
        asm volatile("cp.async.commit_group;\n");
    };

    // Prologue: two stages in flight before any compute.
    issue_full(0, 0);
    issue_full(1, 1);

    // Overlap: compute dist while stages stream in.
    const float kw = TWO_PI / wavelength[w];
    const float cx = center[0];
    const float cy = center[1];
    for (int k = threadIdx.x; k < n; k += TPB) {
        const float2 v = xy[base + k];
        const float dx = v.x - cx;
        const float dy = v.y - cy;
        sdist[k] = sqrtf(fmaf(dx, dx, dy * dy));
    }

    float accC = 0.0f;
    float accS = 0.0f;

    for (int s = 0; s < NSTG; s++) {
        if (s + 1 < NSTG)
            asm volatile("cp.async.wait_group 1;\n" ::: "memory");
        else
            asm volatile("cp.async.wait_group 0;\n" ::: "memory");
        __syncthreads();                     // stage s visible (also covers sdist)

        const int cnt = min(SPTS, n - s * SPTS);
        const float* __restrict__ tb = &stile[s & 1][w];
        const float* __restrict__ dp = &sdist[s * SPTS];

        int i = 0;
        #pragma unroll 2
        for (; i + 4 <= cnt; i += 4) {
            const float d0 = dp[i],     d1 = dp[i + 1];
            const float d2 = dp[i + 2], d3 = dp[i + 3];
            const float t0 = tb[(i)     * NWAVE];
            const float t1 = tb[(i + 1) * NWAVE];
            const float t2 = tb[(i + 2) * NWAVE];
            const float t3 = tb[(i + 3) * NWAVE];
            float sn, cs;
            __sincosf(d0 * kw, &sn, &cs); accC = fmaf(cs, t0, accC); accS = fmaf(sn, t0, accS);
            __sincosf(d1 * kw, &sn, &cs); accC = fmaf(cs, t1, accC); accS = fmaf(sn, t1, accS);
            __sincosf(d2 * kw, &sn, &cs); accC = fmaf(cs, t2, accC); accS = fmaf(sn, t2, accS);
            __sincosf(d3 * kw, &sn, &cs); accC = fmaf(cs, t3, accC); accS = fmaf(sn, t3, accS);
        }
        for (; i < cnt; i++) {
            const float t = tb[i * NWAVE];
            float sn, cs;
            __sincosf(dp[i] * kw, &sn, &cs);
            accC = fmaf(cs, t, accC);
            accS = fmaf(sn, t, accS);
        }
        __syncthreads();                     // everyone done with buffer s&1
        if (s + 2 < NSTG) {
            if (s + 2 == NSTG - 1) issue_tail(s + 2, s & 1);
            else                   issue_full(s + 2, s & 1);
        }
    }

    // Transposed (column) store: scattered but tiny at this NBLK; tail reads
    // contiguous rows.
    g_partialC[w * NBLK + b] = accC;
    g_partialS[w * NBLK + b] = accS;
}

// Tail: R2's exact structure and size (measured ~3.6us wall at NBLK=1184).
__global__ __launch_bounds__(256)
void reduce_kernel()
{
    __shared__ float sc[256];
    __shared__ float ss[256];

    const int w = blockIdx.x;
    const int t = threadIdx.x;

    const float* __restrict__ pc = g_partialC + (size_t)w * NBLK;
    const float* __restrict__ ps = g_partialS + (size_t)w * NBLK;

    float c = 0.0f, s = 0.0f;
    for (int bb = t; bb < NBLK; bb += 256) {   // contiguous rows, coalesced
        c += pc[bb];
        s += ps[bb];
    }
    sc[t] = c;
    ss[t] = s;
    __syncthreads();

    #pragma unroll
    for (int stride = 128; stride > 0; stride >>= 1) {
        if (t < stride) { sc[t] += sc[t + stride]; ss[t] += ss[t + stride]; }
        __syncthreads();
    }

    if (t == 0) {
        const float C = sc[0] * (1.0f / (float)NPOINTS);
        const float S = ss[0] * (1.0f / (float)NPOINTS);
        float m = -3.402823466e38f;
        #pragma unroll
        for (int i = 0; i < NOFFSETS; i++) {
            const float o = (float)i * (TWO_PI / (float)(NOFFSETS - 1));
            const float v = C * cosf(o) - S * sinf(o);
            m = fmaxf(m, v);
        }
        g_m[w] = m;
    }
}

__global__ void final_sum_kernel(float* __restrict__ out)
{
    __shared__ float sm[NWAVE];
    const int w = threadIdx.x;
    sm[w] = g_m[w];
    __syncthreads();

    #pragma unroll
    for (int stride = NWAVE / 2; stride > 0; stride >>= 1) {
        if (w < stride) sm[w] += sm[w + stride];
        __syncthreads();
    }
    if (w == 0) out[0] = -sm[0];
}

extern "C" void kernel_launch(void* const* d_in, const int* in_sizes, int n_in,
                              void* d_out, int out_size)
{
    const float2* xy         = (const float2*)d_in[0];  // [500000, 2]
    const float*  tid        = (const float*) d_in[1];  // [500000, 128]
    const float*  center     = (const float*) d_in[2];  // [2]
    const float*  wavelength = (const float*) d_in[3];  // [128]
    float* out = (float*)d_out;

    accum_kernel<<<NBLK, TPB>>>(xy, tid, center, wavelength);
    reduce_kernel<<<NWAVE, 256>>>();
    final_sum_kernel<<<1, NWAVE>>>(out);
}